// round 5
// baseline (speedup 1.0000x reference)
#include <cuda_runtime.h>
#include <math.h>

// ---------------------------------------------------------------------------
// MainModelAttention: context = softmax((X Wq^T + bq)(X Wk^T + bk)^T / sqrt(128)
//                                       + mask) (X Wv^T + bv)
// B=2, S=4096, H=2048, all fp32.
// Pipeline: 3x GEMM-NT (QKV) -> GEMM-NT (scores, batched) -> softmax rows
//           -> GEMM-NN (P@V, batched, writes d_out).
//
// kernel_launch contains ONLY kernel launches (no runtime API calls): scratch
// buffers are __device__ globals resolved device-side via a selector.
// ---------------------------------------------------------------------------

#define BATCH 2
#define SEQ   4096
#define HID   2048

#define BM 128
#define BN 128
#define BK 8
#define TM 8
#define TN 8
// 256 threads: 16x16 thread grid, each thread owns an 8x8 C micro-tile.

// Scratch (allocation-free: __device__ globals).
__device__ float g_Q[(size_t)BATCH * SEQ * HID];   // 64 MB
__device__ float g_K[(size_t)BATCH * SEQ * HID];   // 64 MB
__device__ float g_V[(size_t)BATCH * SEQ * HID];   // 64 MB
__device__ float g_S[(size_t)BATCH * SEQ * SEQ];   // 128 MB

#define SEL_Q 0
#define SEL_K 1
#define SEL_V 2
#define SEL_S 3
#define SEL_EXT (-1)

__device__ __forceinline__ float* scratch_ptr(int sel) {
    switch (sel) {
        case SEL_Q: return g_Q;
        case SEL_K: return g_K;
        case SEL_V: return g_V;
        default:    return g_S;
    }
}

// ---------------------------------------------------------------------------
// GEMM-NT: C[m,n] = sum_k A[m,k] * B[n,k]  (+ bias[n] if bias != nullptr)
// A: M x K row-major, B: N x K row-major, C: M x N row-major.
// gridDim.z = batch; sA/sB/sC are per-batch element strides.
// M % 128 == 0, N % 128 == 0, K % 8 == 0 (true for all uses here).
// Pointers may come from the harness (sel = -1) or device scratch (sel >= 0).
// ---------------------------------------------------------------------------
__global__ __launch_bounds__(256, 2)
void gemm_nt(const float* __restrict__ Aext, int Asel,
             const float* __restrict__ Bext, int Bsel,
             const float* __restrict__ bias,
             float* __restrict__ Cext, int Csel,
             int M, int N, int K, size_t sA, size_t sB, size_t sC)
{
    const float* A = (Asel < 0) ? Aext : scratch_ptr(Asel);
    const float* Bm = (Bsel < 0) ? Bext : scratch_ptr(Bsel);
    float* C = (Csel < 0) ? Cext : scratch_ptr(Csel);

    __shared__ float As[BK][BM];
    __shared__ float Bs[BK][BN];

    const float* A0 = A + blockIdx.z * sA + (size_t)(blockIdx.y * BM) * K;
    const float* B0 = Bm + blockIdx.z * sB + (size_t)(blockIdx.x * BN) * K;
    float*       C0 = C + blockIdx.z * sC;

    const int tid = threadIdx.x;
    // Global-load mapping: 256 threads cover a 128-row x 8-col (float4) tile.
    const int lr = tid >> 1;          // 0..127 row within tile
    const int lk = (tid & 1) << 2;    // 0 or 4 (k offset, float4)
    const float* Ap = A0 + (size_t)lr * K + lk;
    const float* Bp = B0 + (size_t)lr * K + lk;

    const int tx = tid & 15;          // col group
    const int ty = tid >> 4;          // row group

    float acc[TM][TN];
#pragma unroll
    for (int i = 0; i < TM; i++)
#pragma unroll
        for (int j = 0; j < TN; j++) acc[i][j] = 0.f;

    float4 a4 = *(const float4*)(Ap);
    float4 b4 = *(const float4*)(Bp);

    for (int kt = 0; kt < K; kt += BK) {
        // Transposed store into smem: As[k][m], Bs[k][n]
        As[lk + 0][lr] = a4.x; As[lk + 1][lr] = a4.y;
        As[lk + 2][lr] = a4.z; As[lk + 3][lr] = a4.w;
        Bs[lk + 0][lr] = b4.x; Bs[lk + 1][lr] = b4.y;
        Bs[lk + 2][lr] = b4.z; Bs[lk + 3][lr] = b4.w;
        __syncthreads();

        const int knext = kt + BK;
        if (knext < K) {
            a4 = *(const float4*)(Ap + knext);
            b4 = *(const float4*)(Bp + knext);
        }

#pragma unroll
        for (int kk = 0; kk < BK; kk++) {
            float af[TM], bf[TN];
            *(float4*)&af[0] = *(const float4*)&As[kk][ty * TM];
            *(float4*)&af[4] = *(const float4*)&As[kk][ty * TM + 4];
            *(float4*)&bf[0] = *(const float4*)&Bs[kk][tx * TN];
            *(float4*)&bf[4] = *(const float4*)&Bs[kk][tx * TN + 4];
#pragma unroll
            for (int i = 0; i < TM; i++)
#pragma unroll
                for (int j = 0; j < TN; j++)
                    acc[i][j] = fmaf(af[i], bf[j], acc[i][j]);
        }
        __syncthreads();
    }

    float bvals[TN];
#pragma unroll
    for (int j = 0; j < TN; j++)
        bvals[j] = bias ? bias[blockIdx.x * BN + tx * TN + j] : 0.f;

#pragma unroll
    for (int i = 0; i < TM; i++) {
        const size_t row = (size_t)(blockIdx.y * BM + ty * TM + i);
        float* cp = C0 + row * N + blockIdx.x * BN + tx * TN;
        float4 v0, v1;
        v0.x = acc[i][0] + bvals[0]; v0.y = acc[i][1] + bvals[1];
        v0.z = acc[i][2] + bvals[2]; v0.w = acc[i][3] + bvals[3];
        v1.x = acc[i][4] + bvals[4]; v1.y = acc[i][5] + bvals[5];
        v1.z = acc[i][6] + bvals[6]; v1.w = acc[i][7] + bvals[7];
        *(float4*)cp       = v0;
        *(float4*)(cp + 4) = v1;
    }
}

// ---------------------------------------------------------------------------
// GEMM-NN: C[m,n] = sum_k A[m,k] * B[k,n]
// A = g_S (probs), B = g_V, C = external output.
// ---------------------------------------------------------------------------
__global__ __launch_bounds__(256, 2)
void gemm_nn(float* __restrict__ Cext,
             int M, int N, int K, size_t sA, size_t sB, size_t sC)
{
    const float* A = g_S;
    const float* Bm = g_V;
    float* C = Cext;

    __shared__ float As[BK][BM];
    __shared__ float Bs[BK][BN];

    const float* A0 = A + blockIdx.z * sA + (size_t)(blockIdx.y * BM) * K;
    const float* B0 = Bm + blockIdx.z * sB + (size_t)(blockIdx.x * BN);
    float*       C0 = C + blockIdx.z * sC;

    const int tid = threadIdx.x;
    // A load mapping (row-major, contiguous in k).
    const int lr = tid >> 1;
    const int lk = (tid & 1) << 2;
    const float* Ap = A0 + (size_t)lr * K + lk;
    // B load mapping (row-major in n): 8 k-rows x 32 float4 = 8 x 128.
    const int lkB = tid >> 5;          // 0..7
    const int lnB = (tid & 31) << 2;   // 0..124
    const float* Bp = B0 + (size_t)lkB * N + lnB;

    const int tx = tid & 15;
    const int ty = tid >> 4;

    float acc[TM][TN];
#pragma unroll
    for (int i = 0; i < TM; i++)
#pragma unroll
        for (int j = 0; j < TN; j++) acc[i][j] = 0.f;

    float4 a4 = *(const float4*)(Ap);
    float4 b4 = *(const float4*)(Bp);

    for (int kt = 0; kt < K; kt += BK) {
        As[lk + 0][lr] = a4.x; As[lk + 1][lr] = a4.y;
        As[lk + 2][lr] = a4.z; As[lk + 3][lr] = a4.w;
        *(float4*)&Bs[lkB][lnB] = b4;
        __syncthreads();

        const int knext = kt + BK;
        if (knext < K) {
            a4 = *(const float4*)(Ap + knext);
            b4 = *(const float4*)(Bp + (size_t)knext * N);
        }

#pragma unroll
        for (int kk = 0; kk < BK; kk++) {
            float af[TM], bf[TN];
            *(float4*)&af[0] = *(const float4*)&As[kk][ty * TM];
            *(float4*)&af[4] = *(const float4*)&As[kk][ty * TM + 4];
            *(float4*)&bf[0] = *(const float4*)&Bs[kk][tx * TN];
            *(float4*)&bf[4] = *(const float4*)&Bs[kk][tx * TN + 4];
#pragma unroll
            for (int i = 0; i < TM; i++)
#pragma unroll
                for (int j = 0; j < TN; j++)
                    acc[i][j] = fmaf(af[i], bf[j], acc[i][j]);
        }
        __syncthreads();
    }

#pragma unroll
    for (int i = 0; i < TM; i++) {
        const size_t row = (size_t)(blockIdx.y * BM + ty * TM + i);
        float* cp = C0 + row * N + blockIdx.x * BN + tx * TN;
        float4 v0, v1;
        v0.x = acc[i][0]; v0.y = acc[i][1]; v0.z = acc[i][2]; v0.w = acc[i][3];
        v1.x = acc[i][4]; v1.y = acc[i][5]; v1.z = acc[i][6]; v1.w = acc[i][7];
        *(float4*)cp       = v0;
        *(float4*)(cp + 4) = v1;
    }
}

// ---------------------------------------------------------------------------
// Row softmax over g_S (in place), with scale and additive mask:
//   row'[k] = softmax(row[k] * scale + mask[b, k])
// One block per row; the whole row (4096 floats = 16 KB) is staged in smem.
// ---------------------------------------------------------------------------
__global__ __launch_bounds__(256)
void softmax_rows(const float* __restrict__ mask,
                  int L, int rowsPerBatch, float scale)
{
    __shared__ float buf[SEQ];
    __shared__ float red[8];

    const int row = blockIdx.x;
    const int b = row / rowsPerBatch;
    float* srow = g_S + (size_t)row * L;
    const float* mrow = mask + (size_t)b * L;
    const int tid = threadIdx.x;

    // Pass 1: scale + mask, stage row into smem, thread-local max.
    float lmax = -3.4028235e38f;
    for (int i = tid * 4; i < L; i += 256 * 4) {
        float4 v = *(const float4*)(srow + i);
        float4 m = *(const float4*)(mrow + i);
        v.x = v.x * scale + m.x;
        v.y = v.y * scale + m.y;
        v.z = v.z * scale + m.z;
        v.w = v.w * scale + m.w;
        *(float4*)&buf[i] = v;
        lmax = fmaxf(lmax, fmaxf(fmaxf(v.x, v.y), fmaxf(v.z, v.w)));
    }
#pragma unroll
    for (int o = 16; o; o >>= 1)
        lmax = fmaxf(lmax, __shfl_xor_sync(0xffffffffu, lmax, o));
    if ((tid & 31) == 0) red[tid >> 5] = lmax;
    __syncthreads();
    if (tid < 32) {
        float v = (tid < 8) ? red[tid] : -3.4028235e38f;
#pragma unroll
        for (int o = 4; o; o >>= 1)
            v = fmaxf(v, __shfl_xor_sync(0xffffffffu, v, o));
        if (tid == 0) red[0] = v;
    }
    __syncthreads();
    const float bmax = red[0];
    __syncthreads();  // everyone has read red[0] before it is reused

    // Pass 2: exp + local sum (in smem).
    float lsum = 0.f;
    for (int i = tid * 4; i < L; i += 256 * 4) {
        float4 v = *(float4*)&buf[i];
        v.x = __expf(v.x - bmax);
        v.y = __expf(v.y - bmax);
        v.z = __expf(v.z - bmax);
        v.w = __expf(v.w - bmax);
        *(float4*)&buf[i] = v;
        lsum += v.x + v.y + v.z + v.w;
    }
#pragma unroll
    for (int o = 16; o; o >>= 1)
        lsum += __shfl_xor_sync(0xffffffffu, lsum, o);
    if ((tid & 31) == 0) red[tid >> 5] = lsum;
    __syncthreads();
    if (tid < 32) {
        float v = (tid < 8) ? red[tid] : 0.f;
#pragma unroll
        for (int o = 4; o; o >>= 1)
            v += __shfl_xor_sync(0xffffffffu, v, o);
        if (tid == 0) red[0] = v;
    }
    __syncthreads();
    const float inv = 1.f / red[0];

    // Pass 3: normalize, write back.
    for (int i = tid * 4; i < L; i += 256 * 4) {
        float4 v = *(float4*)&buf[i];
        v.x *= inv; v.y *= inv; v.z *= inv; v.w *= inv;
        *(float4*)(srow + i) = v;
    }
}

// ---------------------------------------------------------------------------
// Launch: pure kernel launches, nothing else.
// ---------------------------------------------------------------------------
extern "C" void kernel_launch(void* const* d_in, const int* in_sizes, int n_in,
                              void* d_out, int out_size)
{
    const float* X    = (const float*)d_in[0];  // [B,S,H]
    const float* mask = (const float*)d_in[1];  // [B,1,S]
    const float* Wq   = (const float*)d_in[2];  // [H,H]
    const float* bq   = (const float*)d_in[3];  // [H]
    const float* Wk   = (const float*)d_in[4];
    const float* bk   = (const float*)d_in[5];
    const float* Wv   = (const float*)d_in[6];
    const float* bv   = (const float*)d_in[7];
    float* out = (float*)d_out;                 // [B,S,H]

    const int M = BATCH * SEQ;                  // 8192
    const size_t strideQKV = (size_t)SEQ * HID; // per-batch stride in Q/K/V
    const size_t strideS   = (size_t)SEQ * SEQ;

    // 1) QKV projections: [8192,2048] x [2048,2048]^T + bias -> scratch
    {
        dim3 grid(HID / BN, M / BM, 1);
        gemm_nt<<<grid, 256>>>(X, SEL_EXT, Wq, SEL_EXT, bq,
                               nullptr, SEL_Q, M, HID, HID, 0, 0, 0);
        gemm_nt<<<grid, 256>>>(X, SEL_EXT, Wk, SEL_EXT, bk,
                               nullptr, SEL_K, M, HID, HID, 0, 0, 0);
        gemm_nt<<<grid, 256>>>(X, SEL_EXT, Wv, SEL_EXT, bv,
                               nullptr, SEL_V, M, HID, HID, 0, 0, 0);
    }

    // 2) Scores = Q @ K^T per batch: [4096,2048] x [4096,2048]^T -> g_S
    {
        dim3 grid(SEQ / BN, SEQ / BM, BATCH);
        gemm_nt<<<grid, 256>>>(nullptr, SEL_Q, nullptr, SEL_K, nullptr,
                               nullptr, SEL_S, SEQ, SEQ, HID,
                               strideQKV, strideQKV, strideS);
    }

    // 3) Softmax rows with scale 1/sqrt(HEAD_SIZE=128) and additive mask.
    {
        const float scale = 0.08838834764831845f;  // 1/sqrt(128)
        softmax_rows<<<BATCH * SEQ, 256>>>(mask, SEQ, SEQ, scale);
    }

    // 4) Context = P @ V per batch: [4096,4096] x [4096,2048] -> d_out
    {
        dim3 grid(HID / BN, SEQ / BM, BATCH);
        gemm_nn<<<grid, 256>>>(out, SEQ, HID, SEQ,
                               strideS, strideQKV, strideQKV);
    }
}

// round 9
// speedup vs baseline: 2.4967x; 2.4967x over previous
#include <cuda_runtime.h>
#include <cuda_bf16.h>
#include <cstdint>

// ===========================================================================
// MainModelAttention via legacy tensor cores (mma.sync bf16, sm_80+ PTX —
// compiles at compute_103; tcgen05 is arch-'a'-gated and rejected by ptxas).
//
// context = softmax((X Wq^T + bq)(X Wk^T + bk)^T / sqrt(128) + mask)(X Wv^T+bv)
// B=2, S=4096, H=2048, fp32 I/O.
//
// Precision: fp32 x = hi + lo (bf16 each), rows stored [hi(0..K-1)|lo(K..2K-1)].
// GEMM accumulates hi*hi + hi*lo + lo*hi in fp32 -> ~2^-18 product error.
// ===========================================================================

#define BATCH 2
#define SEQ   4096
#define HID   2048
#define MROWS (BATCH*SEQ)   // 8192
#define KX    (2*HID)
#define KPV   (2*SEQ)

// ---- scratch (__device__ globals; allocation-free) ----
__device__ __align__(256) __nv_bfloat16 g_Xhl[(size_t)MROWS * KX];
__device__ __align__(256) __nv_bfloat16 g_Whl[3][(size_t)HID * KX];
__device__ __align__(256) float         g_Qf[(size_t)MROWS * HID];
__device__ __align__(256) float         g_Kf[(size_t)MROWS * HID];
__device__ __align__(256) float         g_Vf[(size_t)MROWS * HID];
__device__ __align__(256) __nv_bfloat16 g_Qhl[(size_t)MROWS * KX];
__device__ __align__(256) __nv_bfloat16 g_Khl[(size_t)MROWS * KX];
__device__ __align__(256) __nv_bfloat16 g_Vthl[(size_t)BATCH * HID * KPV];
__device__ __align__(256) float         g_Sf[(size_t)BATCH * SEQ * SEQ];
__device__ __align__(256) __nv_bfloat16 g_Phl[(size_t)BATCH * SEQ * KPV];

enum { SEL_XHL = 0, SEL_WQ, SEL_WK, SEL_WV, SEL_QHL, SEL_KHL, SEL_VTHL, SEL_PHL };
enum { FSEL_QF = 0, FSEL_KF, FSEL_VF, FSEL_SF };

__device__ __forceinline__ __nv_bfloat16* bselw(int s) {
    switch (s) {
        case SEL_XHL:  return g_Xhl;
        case SEL_WQ:   return g_Whl[0];
        case SEL_WK:   return g_Whl[1];
        case SEL_WV:   return g_Whl[2];
        case SEL_QHL:  return g_Qhl;
        case SEL_KHL:  return g_Khl;
        case SEL_VTHL: return g_Vthl;
        default:       return g_Phl;
    }
}
__device__ __forceinline__ float* fselw(int s, float* ext) {
    switch (s) {
        case FSEL_QF: return g_Qf;
        case FSEL_KF: return g_Kf;
        case FSEL_VF: return g_Vf;
        case FSEL_SF: return g_Sf;
        default:      return ext;
    }
}

// ---- PTX helpers (all plain sm_80/sm_75 features) ----
__device__ __forceinline__ uint32_t smem_to_u32(const void* p) {
    uint32_t a;
    asm("{ .reg .u64 t; cvta.to.shared.u64 t, %1; cvt.u32.u64 %0, t; }"
        : "=r"(a) : "l"(p));
    return a;
}
#define CP_ASYNC16(dst, src) \
    asm volatile("cp.async.cg.shared.global [%0], [%1], 16;" :: "r"(dst), "l"(src))
#define CP_COMMIT() asm volatile("cp.async.commit_group;" ::: "memory")
#define CP_WAIT0()  asm volatile("cp.async.wait_group 0;" ::: "memory")
#define CP_WAIT1()  asm volatile("cp.async.wait_group 1;" ::: "memory")

__device__ __forceinline__ void ldsm4(uint32_t r[4], uint32_t a) {
    asm volatile("ldmatrix.sync.aligned.m8n8.x4.shared.b16 {%0,%1,%2,%3}, [%4];"
                 : "=r"(r[0]), "=r"(r[1]), "=r"(r[2]), "=r"(r[3]) : "r"(a));
}
__device__ __forceinline__ void mma_bf16(float d[4], const uint32_t a[4],
                                         const uint32_t b0, const uint32_t b1) {
    asm volatile(
        "mma.sync.aligned.m16n8k16.row.col.f32.bf16.bf16.f32 "
        "{%0,%1,%2,%3}, {%4,%5,%6,%7}, {%8,%9}, {%0,%1,%2,%3};"
        : "+f"(d[0]), "+f"(d[1]), "+f"(d[2]), "+f"(d[3])
        : "r"(a[0]), "r"(a[1]), "r"(a[2]), "r"(a[3]), "r"(b0), "r"(b1));
}

// ===========================================================================
// GEMM-NT bf16 hi/lo (HMMA): C[m,n] = sum_k (Ahi+Alo)[m,k]*(Bhi+Blo)[n,k]
// Tile 128x128, BK=32, 8 warps (2x4) of 64x32 warp tiles, double-buffered
// cp.async stages. SMEM rows have 80-byte stride -> conflict-free ldmatrix.
// ===========================================================================
#define ROWB    80
#define TILE_B  (128 * ROWB)           // 10240 per tile
#define STAGE_B (4 * TILE_B)           // 40960 per stage (Ahi,Alo,Bhi,Blo)
#define GEMM_SMEM (2 * STAGE_B)        // 81920

__device__ __forceinline__ void stage_loads(
    uint32_t smStage, const __nv_bfloat16* Ahi, const __nv_bfloat16* Alo,
    const __nv_bfloat16* Bhi, const __nv_bfloat16* Blo, size_t ld, int tid)
{
#pragma unroll
    for (int j = 0; j < 2; j++) {
        const int within = j * 256 + tid;      // 0..511
        const int r = within >> 2, c = within & 3;
        const size_t go = (size_t)r * ld + c * 8;
        const uint32_t so = (uint32_t)(r * ROWB + c * 16);
        CP_ASYNC16(smStage + 0 * TILE_B + so, Ahi + go);
        CP_ASYNC16(smStage + 1 * TILE_B + so, Alo + go);
        CP_ASYNC16(smStage + 2 * TILE_B + so, Bhi + go);
        CP_ASYNC16(smStage + 3 * TILE_B + so, Blo + go);
    }
}

__global__ void __launch_bounds__(256)
gemm_hmma(int Asel, int Bsel, const float* __restrict__ bias,
          int Csel, float* __restrict__ Cext,
          int Korig, int N, size_t sA, size_t sB, size_t sC)
{
    extern __shared__ __align__(16) char sm[];
    const uint32_t smb = smem_to_u32(sm);
    const int tid = threadIdx.x;
    const int lane = tid & 31, warp = tid >> 5;
    const size_t ld = (size_t)2 * Korig;

    const __nv_bfloat16* A = bselw(Asel) + blockIdx.z * sA + (size_t)blockIdx.y * 128 * ld;
    const __nv_bfloat16* B = bselw(Bsel) + blockIdx.z * sB + (size_t)blockIdx.x * 128 * ld;
    float* C = fselw(Csel, Cext) + blockIdx.z * sC;

    const int m0 = (warp >> 2) * 64;     // warp tile origin
    const int n0 = (warp & 3) * 32;

    // ldmatrix lane offsets (bytes within a tile)
    const uint32_t aLane = (uint32_t)((m0 + (lane & 15)) * ROWB + ((lane >> 4) << 4));
    const uint32_t bLane = (uint32_t)((n0 + ((lane >> 4) << 3) + (lane & 7)) * ROWB
                                      + (((lane >> 3) & 1) << 4));

    float acc[4][4][4];
#pragma unroll
    for (int i = 0; i < 4; i++)
#pragma unroll
        for (int j = 0; j < 4; j++)
#pragma unroll
            for (int q = 0; q < 4; q++) acc[i][j][q] = 0.f;

    const int T = Korig / 32;
    stage_loads(smb, A, A + Korig, B, B + Korig, ld, tid);
    CP_COMMIT();

    for (int t = 0; t < T; t++) {
        if (t + 1 < T) {
            const int kt = (t + 1) * 32;
            stage_loads(smb + ((t + 1) & 1) * STAGE_B,
                        A + kt, A + Korig + kt, B + kt, B + Korig + kt, ld, tid);
            CP_COMMIT();
            CP_WAIT1();
        } else {
            CP_WAIT0();
        }
        __syncthreads();

        const uint32_t stage = smb + (t & 1) * STAGE_B;
#pragma unroll
        for (int kh = 0; kh < 2; kh++) {
            uint32_t ah[4][4], al[4][4], bh[2][4], bl[2][4];
            const uint32_t aAddr = stage + aLane + kh * 32;
#pragma unroll
            for (int mt = 0; mt < 4; mt++) {
                ldsm4(ah[mt], aAddr + mt * (16 * ROWB));
                ldsm4(al[mt], aAddr + mt * (16 * ROWB) + TILE_B);
            }
            const uint32_t bAddr = stage + 2 * TILE_B + bLane + kh * 32;
#pragma unroll
            for (int nt = 0; nt < 2; nt++) {
                ldsm4(bh[nt], bAddr + nt * (16 * ROWB));
                ldsm4(bl[nt], bAddr + nt * (16 * ROWB) + TILE_B);
            }
            // pass 1: hi*hi
#pragma unroll
            for (int mt = 0; mt < 4; mt++)
#pragma unroll
                for (int n8 = 0; n8 < 4; n8++)
                    mma_bf16(acc[mt][n8], ah[mt], bh[n8 >> 1][(n8 & 1) * 2],
                             bh[n8 >> 1][(n8 & 1) * 2 + 1]);
            // pass 2: hi*lo
#pragma unroll
            for (int mt = 0; mt < 4; mt++)
#pragma unroll
                for (int n8 = 0; n8 < 4; n8++)
                    mma_bf16(acc[mt][n8], ah[mt], bl[n8 >> 1][(n8 & 1) * 2],
                             bl[n8 >> 1][(n8 & 1) * 2 + 1]);
            // pass 3: lo*hi
#pragma unroll
            for (int mt = 0; mt < 4; mt++)
#pragma unroll
                for (int n8 = 0; n8 < 4; n8++)
                    mma_bf16(acc[mt][n8], al[mt], bh[n8 >> 1][(n8 & 1) * 2],
                             bh[n8 >> 1][(n8 & 1) * 2 + 1]);
        }
        __syncthreads();
    }

    // Epilogue: acc -> C (+bias). Fragment: c0,c1=(g,2t),(g,2t+1); c2,c3=row g+8.
    const int g = lane >> 2, tq = lane & 3;
#pragma unroll
    for (int mt = 0; mt < 4; mt++) {
        const size_t r0 = (size_t)blockIdx.y * 128 + m0 + mt * 16 + g;
#pragma unroll
        for (int n8 = 0; n8 < 4; n8++) {
            const size_t col = (size_t)blockIdx.x * 128 + n0 + n8 * 8 + 2 * tq;
            float b0 = 0.f, b1 = 0.f;
            if (bias) { b0 = bias[col]; b1 = bias[col + 1]; }
            float2 v0 = { acc[mt][n8][0] + b0, acc[mt][n8][1] + b1 };
            float2 v1 = { acc[mt][n8][2] + b0, acc[mt][n8][3] + b1 };
            *(float2*)(C + r0 * N + col) = v0;
            *(float2*)(C + (r0 + 8) * N + col) = v1;
        }
    }
}

// ===========================================================================
// fp32 -> bf16 hi/lo convert: out row r = [hi(0..C-1) | lo(C..2C-1)]
// ===========================================================================
__global__ void __launch_bounds__(256)
cvt_hilo(const float* __restrict__ inExt, int inSel, int outSel, int C, size_t n)
{
    size_t i = (size_t)blockIdx.x * 256 + threadIdx.x;
    if (i >= n) return;
    const float* in = (inSel < 0) ? inExt : fselw(inSel, nullptr);
    __nv_bfloat16* out = bselw(outSel);
    size_t r = i / (size_t)C, c = i - r * (size_t)C;
    float x = in[i];
    __nv_bfloat16 h = __float2bfloat16(x);
    __nv_bfloat16 lo = __float2bfloat16(x - __bfloat162float(h));
    out[r * (size_t)(2 * C) + c] = h;
    out[r * (size_t)(2 * C) + C + c] = lo;
}

// ===========================================================================
// V transpose + hi/lo: Vf [b][s][h] -> Vthl [b][h][hi(s)|lo(s)]
// ===========================================================================
__global__ void __launch_bounds__(256)
transpose_cvt_v()
{
    __shared__ float tile[32][33];
    const int zb = blockIdx.z;
    const float* in = g_Vf + (size_t)zb * SEQ * HID;
    __nv_bfloat16* out = g_Vthl + (size_t)zb * HID * KPV;
    const int s0 = blockIdx.x * 32, h0 = blockIdx.y * 32;
    const int tx = threadIdx.x & 31, ty = threadIdx.x >> 5;
#pragma unroll
    for (int j = 0; j < 32; j += 8)
        tile[ty + j][tx] = in[(size_t)(s0 + ty + j) * HID + h0 + tx];
    __syncthreads();
#pragma unroll
    for (int j = 0; j < 32; j += 8) {
        float x = tile[tx][ty + j];
        __nv_bfloat16 h = __float2bfloat16(x);
        __nv_bfloat16 lo = __float2bfloat16(x - __bfloat162float(h));
        out[(size_t)(h0 + ty + j) * KPV + (s0 + tx)] = h;
        out[(size_t)(h0 + ty + j) * KPV + SEQ + (s0 + tx)] = lo;
    }
}

// ===========================================================================
// Row softmax: P = softmax(S*scale + mask) written as bf16 hi/lo [S|S].
// ===========================================================================
__global__ void __launch_bounds__(256)
softmax_rows(const float* __restrict__ mask, float scale)
{
    __shared__ float buf[SEQ];
    __shared__ float red[8];

    const int row = blockIdx.x;
    const int b = row / SEQ;
    const float* srow = g_Sf + (size_t)row * SEQ;
    __nv_bfloat16* prow = g_Phl + (size_t)row * KPV;
    const float* mrow = mask + (size_t)b * SEQ;
    const int tid = threadIdx.x;

    float lmax = -3.4028235e38f;
    for (int i = tid * 4; i < SEQ; i += 256 * 4) {
        float4 v = *(const float4*)(srow + i);
        float4 m = *(const float4*)(mrow + i);
        v.x = v.x * scale + m.x; v.y = v.y * scale + m.y;
        v.z = v.z * scale + m.z; v.w = v.w * scale + m.w;
        *(float4*)&buf[i] = v;
        lmax = fmaxf(lmax, fmaxf(fmaxf(v.x, v.y), fmaxf(v.z, v.w)));
    }
#pragma unroll
    for (int o = 16; o; o >>= 1)
        lmax = fmaxf(lmax, __shfl_xor_sync(0xffffffffu, lmax, o));
    if ((tid & 31) == 0) red[tid >> 5] = lmax;
    __syncthreads();
    if (tid < 32) {
        float v = (tid < 8) ? red[tid] : -3.4028235e38f;
#pragma unroll
        for (int o = 4; o; o >>= 1)
            v = fmaxf(v, __shfl_xor_sync(0xffffffffu, v, o));
        if (tid == 0) red[0] = v;
    }
    __syncthreads();
    const float bmax = red[0];
    __syncthreads();

    float lsum = 0.f;
    for (int i = tid * 4; i < SEQ; i += 256 * 4) {
        float4 v = *(float4*)&buf[i];
        v.x = __expf(v.x - bmax); v.y = __expf(v.y - bmax);
        v.z = __expf(v.z - bmax); v.w = __expf(v.w - bmax);
        *(float4*)&buf[i] = v;
        lsum += v.x + v.y + v.z + v.w;
    }
#pragma unroll
    for (int o = 16; o; o >>= 1)
        lsum += __shfl_xor_sync(0xffffffffu, lsum, o);
    if ((tid & 31) == 0) red[tid >> 5] = lsum;
    __syncthreads();
    if (tid < 32) {
        float v = (tid < 8) ? red[tid] : 0.f;
#pragma unroll
        for (int o = 4; o; o >>= 1)
            v += __shfl_xor_sync(0xffffffffu, v, o);
        if (tid == 0) red[0] = v;
    }
    __syncthreads();
    const float inv = 1.f / red[0];

    for (int i = tid * 4; i < SEQ; i += 256 * 4) {
        float4 v = *(float4*)&buf[i];
        v.x *= inv; v.y *= inv; v.z *= inv; v.w *= inv;
#pragma unroll
        for (int q = 0; q < 4; q++) {
            float x = (&v.x)[q];
            __nv_bfloat16 h = __float2bfloat16(x);
            __nv_bfloat16 lo = __float2bfloat16(x - __bfloat162float(h));
            prow[i + q] = h;
            prow[SEQ + i + q] = lo;
        }
    }
}

// ===========================================================================
// Launch
// ===========================================================================
extern "C" void kernel_launch(void* const* d_in, const int* in_sizes, int n_in,
                              void* d_out, int out_size)
{
    const float* X    = (const float*)d_in[0];
    const float* mask = (const float*)d_in[1];
    const float* Wq   = (const float*)d_in[2];
    const float* bq   = (const float*)d_in[3];
    const float* Wk   = (const float*)d_in[4];
    const float* bk   = (const float*)d_in[5];
    const float* Wv   = (const float*)d_in[6];
    const float* bv   = (const float*)d_in[7];
    float* out = (float*)d_out;

    cudaFuncSetAttribute(gemm_hmma, cudaFuncAttributeMaxDynamicSharedMemorySize,
                         GEMM_SMEM);

    // 1) hi/lo converts of inputs
    {
        const size_t nX = (size_t)MROWS * HID;
        const size_t nW = (size_t)HID * HID;
        cvt_hilo<<<(unsigned)((nX + 255) / 256), 256>>>(X,  -1, SEL_XHL, HID, nX);
        cvt_hilo<<<(unsigned)((nW + 255) / 256), 256>>>(Wq, -1, SEL_WQ,  HID, nW);
        cvt_hilo<<<(unsigned)((nW + 255) / 256), 256>>>(Wk, -1, SEL_WK,  HID, nW);
        cvt_hilo<<<(unsigned)((nW + 255) / 256), 256>>>(Wv, -1, SEL_WV,  HID, nW);
    }

    // 2) QKV projections: [8192,2048]x[2048,2048]^T + bias -> fp32
    {
        dim3 g(HID / 128, MROWS / 128, 1);
        gemm_hmma<<<g, 256, GEMM_SMEM>>>(SEL_XHL, SEL_WQ, bq, FSEL_QF, nullptr,
                                         HID, HID, 0, 0, 0);
        gemm_hmma<<<g, 256, GEMM_SMEM>>>(SEL_XHL, SEL_WK, bk, FSEL_KF, nullptr,
                                         HID, HID, 0, 0, 0);
        gemm_hmma<<<g, 256, GEMM_SMEM>>>(SEL_XHL, SEL_WV, bv, FSEL_VF, nullptr,
                                         HID, HID, 0, 0, 0);
    }

    // 3) Re-split Q,K; transpose+split V
    {
        const size_t nQ = (size_t)MROWS * HID;
        cvt_hilo<<<(unsigned)((nQ + 255) / 256), 256>>>(nullptr, FSEL_QF, SEL_QHL, HID, nQ);
        cvt_hilo<<<(unsigned)((nQ + 255) / 256), 256>>>(nullptr, FSEL_KF, SEL_KHL, HID, nQ);
        transpose_cvt_v<<<dim3(SEQ / 32, HID / 32, BATCH), 256>>>();
    }

    // 4) Scores = Q @ K^T per batch -> g_Sf
    {
        dim3 g(SEQ / 128, SEQ / 128, BATCH);
        gemm_hmma<<<g, 256, GEMM_SMEM>>>(SEL_QHL, SEL_KHL, nullptr, FSEL_SF, nullptr,
                                         HID, SEQ,
                                         (size_t)SEQ * KX, (size_t)SEQ * KX,
                                         (size_t)SEQ * SEQ);
    }

    // 5) Softmax -> g_Phl
    softmax_rows<<<MROWS, 256>>>(mask, 0.08838834764831845f);

    // 6) Context = P @ Vt^T per batch -> d_out
    {
        dim3 g(HID / 128, SEQ / 128, BATCH);
        gemm_hmma<<<g, 256, GEMM_SMEM>>>(SEL_PHL, SEL_VTHL, nullptr, -1, out,
                                         SEQ, HID,
                                         (size_t)SEQ * KPV, (size_t)HID * KPV,
                                         (size_t)SEQ * HID);
    }
}

// round 10
// speedup vs baseline: 2.6493x; 1.0611x over previous
#include <cuda_runtime.h>
#include <cuda_bf16.h>
#include <cstdint>

// ===========================================================================
// MainModelAttention via legacy tensor cores (mma.sync bf16, plain sm_80 PTX).
// context = softmax((X Wq^T + bq)(X Wk^T + bk)^T / sqrt(128) + mask)(X Wv^T+bv)
// B=2, S=4096, H=2048, fp32 I/O.
//
// Precision: fp32 x = hi + lo (bf16 each), rows stored [hi(0..K-1)|lo(K..2K-1)].
// GEMM accumulates hi*hi + hi*lo + lo*hi in fp32 -> ~2^-18 product error.
//
// R10: BK=64 (half the barriers), fused hi/lo epilogue for Q/K, fused
// scale+mask in scores epilogue, vectorized converts.
// ===========================================================================

#define BATCH 2
#define SEQ   4096
#define HID   2048
#define MROWS (BATCH*SEQ)   // 8192
#define KX    (2*HID)
#define KPV   (2*SEQ)

// ---- scratch (__device__ globals; allocation-free) ----
__device__ __align__(256) __nv_bfloat16 g_Xhl[(size_t)MROWS * KX];
__device__ __align__(256) __nv_bfloat16 g_Whl[3][(size_t)HID * KX];
__device__ __align__(256) float         g_Vf[(size_t)MROWS * HID];
__device__ __align__(256) __nv_bfloat16 g_Qhl[(size_t)MROWS * KX];
__device__ __align__(256) __nv_bfloat16 g_Khl[(size_t)MROWS * KX];
__device__ __align__(256) __nv_bfloat16 g_Vthl[(size_t)BATCH * HID * KPV];
__device__ __align__(256) float         g_Sf[(size_t)BATCH * SEQ * SEQ];
__device__ __align__(256) __nv_bfloat16 g_Phl[(size_t)BATCH * SEQ * KPV];

enum { SEL_XHL = 0, SEL_WQ, SEL_WK, SEL_WV, SEL_QHL, SEL_KHL, SEL_VTHL, SEL_PHL };
enum { FSEL_VF = 0, FSEL_SF };

__device__ __forceinline__ __nv_bfloat16* bselw(int s) {
    switch (s) {
        case SEL_XHL:  return g_Xhl;
        case SEL_WQ:   return g_Whl[0];
        case SEL_WK:   return g_Whl[1];
        case SEL_WV:   return g_Whl[2];
        case SEL_QHL:  return g_Qhl;
        case SEL_KHL:  return g_Khl;
        case SEL_VTHL: return g_Vthl;
        default:       return g_Phl;
    }
}
__device__ __forceinline__ float* fselw(int s, float* ext) {
    switch (s) {
        case FSEL_VF: return g_Vf;
        case FSEL_SF: return g_Sf;
        default:      return ext;
    }
}

// ---- PTX helpers ----
__device__ __forceinline__ uint32_t smem_to_u32(const void* p) {
    uint32_t a;
    asm("{ .reg .u64 t; cvta.to.shared.u64 t, %1; cvt.u32.u64 %0, t; }"
        : "=r"(a) : "l"(p));
    return a;
}
#define CP_ASYNC16(dst, src) \
    asm volatile("cp.async.cg.shared.global [%0], [%1], 16;" :: "r"(dst), "l"(src))
#define CP_COMMIT() asm volatile("cp.async.commit_group;" ::: "memory")
#define CP_WAIT0()  asm volatile("cp.async.wait_group 0;" ::: "memory")
#define CP_WAIT1()  asm volatile("cp.async.wait_group 1;" ::: "memory")

__device__ __forceinline__ void ldsm4(uint32_t r[4], uint32_t a) {
    asm volatile("ldmatrix.sync.aligned.m8n8.x4.shared.b16 {%0,%1,%2,%3}, [%4];"
                 : "=r"(r[0]), "=r"(r[1]), "=r"(r[2]), "=r"(r[3]) : "r"(a));
}
__device__ __forceinline__ void mma_bf16(float d[4], const uint32_t a[4],
                                         const uint32_t b0, const uint32_t b1) {
    asm volatile(
        "mma.sync.aligned.m16n8k16.row.col.f32.bf16.bf16.f32 "
        "{%0,%1,%2,%3}, {%4,%5,%6,%7}, {%8,%9}, {%0,%1,%2,%3};"
        : "+f"(d[0]), "+f"(d[1]), "+f"(d[2]), "+f"(d[3])
        : "r"(a[0]), "r"(a[1]), "r"(a[2]), "r"(a[3]), "r"(b0), "r"(b1));
}

__device__ __forceinline__ uint32_t pack_hi(float a, float b, uint32_t& lo) {
    __nv_bfloat16 ha = __float2bfloat16(a);
    __nv_bfloat16 hb = __float2bfloat16(b);
    __nv_bfloat162 l;
    l.x = __float2bfloat16(a - __bfloat162float(ha));
    l.y = __float2bfloat16(b - __bfloat162float(hb));
    lo = *reinterpret_cast<uint32_t*>(&l);
    __nv_bfloat162 h; h.x = ha; h.y = hb;
    return *reinterpret_cast<uint32_t*>(&h);
}

// ===========================================================================
// GEMM-NT bf16 hi/lo (HMMA): C[m,n] = sum_k (Ahi+Alo)[m,k]*(Bhi+Blo)[n,k]
// Tile 128x128, BK=64, 8 warps (2x4) of 64x32 warp tiles, double-buffered
// cp.async. ROWB=144 (128B data + 16B pad): 144/16==9 => 9 mod 8 == 1 =>
// 8 consecutive rows hit 8 distinct 16B columns -> conflict-free ldmatrix.
// Epilogue modes: 0 = fp32 (+bias); 1 = bf16 hi/lo into bselw(Csel);
//                 2 = fp32 * scale + mask[z*N + col].
// ===========================================================================
#define ROWB    144
#define TILE_B  (128 * ROWB)           // 18432
#define STAGE_B (4 * TILE_B)           // 73728 (Ahi,Alo,Bhi,Blo)
#define GEMM_SMEM (2 * STAGE_B)        // 147456

__device__ __forceinline__ void stage_loads(
    uint32_t smStage, const __nv_bfloat16* Ahi, const __nv_bfloat16* Alo,
    const __nv_bfloat16* Bhi, const __nv_bfloat16* Blo, size_t ld, int tid)
{
#pragma unroll
    for (int j = 0; j < 4; j++) {
        const int within = j * 256 + tid;      // 0..1023
        const int r = within >> 3, c = within & 7;
        const size_t go = (size_t)r * ld + c * 8;
        const uint32_t so = (uint32_t)(r * ROWB + c * 16);
        CP_ASYNC16(smStage + 0 * TILE_B + so, Ahi + go);
        CP_ASYNC16(smStage + 1 * TILE_B + so, Alo + go);
        CP_ASYNC16(smStage + 2 * TILE_B + so, Bhi + go);
        CP_ASYNC16(smStage + 3 * TILE_B + so, Blo + go);
    }
}

__global__ void __launch_bounds__(256)
gemm_hmma(int Asel, int Bsel, const float* __restrict__ bias,
          int emode, int Csel, float* __restrict__ Cext,
          const float* __restrict__ mask, float scale,
          int Korig, int N, size_t sA, size_t sB, size_t sC)
{
    extern __shared__ __align__(16) char sm[];
    const uint32_t smb = smem_to_u32(sm);
    const int tid = threadIdx.x;
    const int lane = tid & 31, warp = tid >> 5;
    const size_t ld = (size_t)2 * Korig;

    const __nv_bfloat16* A = bselw(Asel) + blockIdx.z * sA + (size_t)blockIdx.y * 128 * ld;
    const __nv_bfloat16* B = bselw(Bsel) + blockIdx.z * sB + (size_t)blockIdx.x * 128 * ld;

    const int m0 = (warp >> 2) * 64;     // warp tile origin
    const int n0 = (warp & 3) * 32;

    const uint32_t aLane = (uint32_t)((m0 + (lane & 15)) * ROWB + ((lane >> 4) << 4));
    const uint32_t bLane = (uint32_t)((n0 + ((lane >> 4) << 3) + (lane & 7)) * ROWB
                                      + (((lane >> 3) & 1) << 4));

    float acc[4][4][4];
#pragma unroll
    for (int i = 0; i < 4; i++)
#pragma unroll
        for (int j = 0; j < 4; j++)
#pragma unroll
            for (int q = 0; q < 4; q++) acc[i][j][q] = 0.f;

    const int T = Korig / 64;
    stage_loads(smb, A, A + Korig, B, B + Korig, ld, tid);
    CP_COMMIT();

    for (int t = 0; t < T; t++) {
        if (t + 1 < T) {
            const int kt = (t + 1) * 64;
            stage_loads(smb + ((t + 1) & 1) * STAGE_B,
                        A + kt, A + Korig + kt, B + kt, B + Korig + kt, ld, tid);
            CP_COMMIT();
            CP_WAIT1();
        } else {
            CP_WAIT0();
        }
        __syncthreads();

        const uint32_t stage = smb + (t & 1) * STAGE_B;
#pragma unroll
        for (int kh = 0; kh < 4; kh++) {
            uint32_t ah[4][4], al[4][4], bh[2][4], bl[2][4];
            const uint32_t aAddr = stage + aLane + kh * 32;
#pragma unroll
            for (int mt = 0; mt < 4; mt++) {
                ldsm4(ah[mt], aAddr + mt * (16 * ROWB));
                ldsm4(al[mt], aAddr + mt * (16 * ROWB) + TILE_B);
            }
            const uint32_t bAddr = stage + 2 * TILE_B + bLane + kh * 32;
#pragma unroll
            for (int nt = 0; nt < 2; nt++) {
                ldsm4(bh[nt], bAddr + nt * (16 * ROWB));
                ldsm4(bl[nt], bAddr + nt * (16 * ROWB) + TILE_B);
            }
            // pass 1: hi*hi
#pragma unroll
            for (int mt = 0; mt < 4; mt++)
#pragma unroll
                for (int n8 = 0; n8 < 4; n8++)
                    mma_bf16(acc[mt][n8], ah[mt], bh[n8 >> 1][(n8 & 1) * 2],
                             bh[n8 >> 1][(n8 & 1) * 2 + 1]);
            // pass 2: hi*lo
#pragma unroll
            for (int mt = 0; mt < 4; mt++)
#pragma unroll
                for (int n8 = 0; n8 < 4; n8++)
                    mma_bf16(acc[mt][n8], ah[mt], bl[n8 >> 1][(n8 & 1) * 2],
                             bl[n8 >> 1][(n8 & 1) * 2 + 1]);
            // pass 3: lo*hi
#pragma unroll
            for (int mt = 0; mt < 4; mt++)
#pragma unroll
                for (int n8 = 0; n8 < 4; n8++)
                    mma_bf16(acc[mt][n8], al[mt], bh[n8 >> 1][(n8 & 1) * 2],
                             bh[n8 >> 1][(n8 & 1) * 2 + 1]);
        }
        __syncthreads();
    }

    // Epilogue. Fragment: c0,c1 = (row g, col 2t / 2t+1); c2,c3 = row g+8.
    const int g = lane >> 2, tq = lane & 3;
    if (emode == 1) {
        // bf16 hi/lo output rows of width 2N: [hi | lo]
        __nv_bfloat16* O = bselw(Csel) + blockIdx.z * sC;
        const size_t W2 = (size_t)2 * N;
#pragma unroll
        for (int mt = 0; mt < 4; mt++) {
            const size_t r0 = (size_t)blockIdx.y * 128 + m0 + mt * 16 + g;
#pragma unroll
            for (int n8 = 0; n8 < 4; n8++) {
                const size_t col = (size_t)blockIdx.x * 128 + n0 + n8 * 8 + 2 * tq;
                float b0 = 0.f, b1 = 0.f;
                if (bias) { b0 = bias[col]; b1 = bias[col + 1]; }
                uint32_t lo0, lo1;
                const uint32_t h0 = pack_hi(acc[mt][n8][0] + b0, acc[mt][n8][1] + b1, lo0);
                const uint32_t h1 = pack_hi(acc[mt][n8][2] + b0, acc[mt][n8][3] + b1, lo1);
                *(uint32_t*)(O + r0 * W2 + col)             = h0;
                *(uint32_t*)(O + r0 * W2 + N + col)         = lo0;
                *(uint32_t*)(O + (r0 + 8) * W2 + col)       = h1;
                *(uint32_t*)(O + (r0 + 8) * W2 + N + col)   = lo1;
            }
        }
    } else {
        float* C = fselw(Csel, Cext) + blockIdx.z * sC;
#pragma unroll
        for (int mt = 0; mt < 4; mt++) {
            const size_t r0 = (size_t)blockIdx.y * 128 + m0 + mt * 16 + g;
#pragma unroll
            for (int n8 = 0; n8 < 4; n8++) {
                const size_t col = (size_t)blockIdx.x * 128 + n0 + n8 * 8 + 2 * tq;
                float b0 = 0.f, b1 = 0.f;
                if (emode == 2) {
                    b0 = mask[(size_t)blockIdx.z * N + col];
                    b1 = mask[(size_t)blockIdx.z * N + col + 1];
                } else if (bias) {
                    b0 = bias[col]; b1 = bias[col + 1];
                }
                const float s = (emode == 2) ? scale : 1.f;
                float2 v0 = { acc[mt][n8][0] * s + b0, acc[mt][n8][1] * s + b1 };
                float2 v1 = { acc[mt][n8][2] * s + b0, acc[mt][n8][3] * s + b1 };
                *(float2*)(C + r0 * N + col) = v0;
                *(float2*)(C + (r0 + 8) * N + col) = v1;
            }
        }
    }
}

// ===========================================================================
// fp32 -> bf16 hi/lo convert, 8 elements/thread (vectorized).
// out row r = [hi(0..C-1) | lo(C..2C-1)]; C % 8 == 0, n % 8 == 0.
// ===========================================================================
__global__ void __launch_bounds__(256)
cvt_hilo8(const float* __restrict__ in, int outSel, int C, size_t n)
{
    const size_t i = ((size_t)blockIdx.x * 256 + threadIdx.x) * 8;
    if (i >= n) return;
    __nv_bfloat16* out = bselw(outSel);
    const size_t r = i / (size_t)C, c = i - r * (size_t)C;

    float4 v0 = *(const float4*)(in + i);
    float4 v1 = *(const float4*)(in + i + 4);
    uint32_t h[4], l[4];
    h[0] = pack_hi(v0.x, v0.y, l[0]);
    h[1] = pack_hi(v0.z, v0.w, l[1]);
    h[2] = pack_hi(v1.x, v1.y, l[2]);
    h[3] = pack_hi(v1.z, v1.w, l[3]);
    __nv_bfloat16* oh = out + r * (size_t)(2 * C) + c;
    *(uint4*)oh       = *(uint4*)h;
    *(uint4*)(oh + C) = *(uint4*)l;
}

// ===========================================================================
// V transpose + hi/lo: Vf [b][s][h] -> Vthl [b][h][hi(s)|lo(s)]
// ===========================================================================
__global__ void __launch_bounds__(256)
transpose_cvt_v()
{
    __shared__ float tile[32][33];
    const int zb = blockIdx.z;
    const float* in = g_Vf + (size_t)zb * SEQ * HID;
    __nv_bfloat16* out = g_Vthl + (size_t)zb * HID * KPV;
    const int s0 = blockIdx.x * 32, h0 = blockIdx.y * 32;
    const int tx = threadIdx.x & 31, ty = threadIdx.x >> 5;
#pragma unroll
    for (int j = 0; j < 32; j += 8)
        tile[ty + j][tx] = in[(size_t)(s0 + ty + j) * HID + h0 + tx];
    __syncthreads();
#pragma unroll
    for (int j = 0; j < 32; j += 8) {
        float x = tile[tx][ty + j];
        __nv_bfloat16 h = __float2bfloat16(x);
        __nv_bfloat16 lo = __float2bfloat16(x - __bfloat162float(h));
        out[(size_t)(h0 + ty + j) * KPV + (s0 + tx)] = h;
        out[(size_t)(h0 + ty + j) * KPV + SEQ + (s0 + tx)] = lo;
    }
}

// ===========================================================================
// Row softmax over pre-scaled+masked scores: P = softmax(S) as bf16 hi/lo.
// ===========================================================================
__global__ void __launch_bounds__(256)
softmax_rows()
{
    __shared__ float buf[SEQ];
    __shared__ float red[8];

    const int row = blockIdx.x;
    const float* srow = g_Sf + (size_t)row * SEQ;
    __nv_bfloat16* prow = g_Phl + (size_t)row * KPV;
    const int tid = threadIdx.x;

    float lmax = -3.4028235e38f;
    for (int i = tid * 4; i < SEQ; i += 256 * 4) {
        float4 v = *(const float4*)(srow + i);
        *(float4*)&buf[i] = v;
        lmax = fmaxf(lmax, fmaxf(fmaxf(v.x, v.y), fmaxf(v.z, v.w)));
    }
#pragma unroll
    for (int o = 16; o; o >>= 1)
        lmax = fmaxf(lmax, __shfl_xor_sync(0xffffffffu, lmax, o));
    if ((tid & 31) == 0) red[tid >> 5] = lmax;
    __syncthreads();
    if (tid < 32) {
        float v = (tid < 8) ? red[tid] : -3.4028235e38f;
#pragma unroll
        for (int o = 4; o; o >>= 1)
            v = fmaxf(v, __shfl_xor_sync(0xffffffffu, v, o));
        if (tid == 0) red[0] = v;
    }
    __syncthreads();
    const float bmax = red[0];
    __syncthreads();

    float lsum = 0.f;
    for (int i = tid * 4; i < SEQ; i += 256 * 4) {
        float4 v = *(float4*)&buf[i];
        v.x = __expf(v.x - bmax); v.y = __expf(v.y - bmax);
        v.z = __expf(v.z - bmax); v.w = __expf(v.w - bmax);
        *(float4*)&buf[i] = v;
        lsum += v.x + v.y + v.z + v.w;
    }
#pragma unroll
    for (int o = 16; o; o >>= 1)
        lsum += __shfl_xor_sync(0xffffffffu, lsum, o);
    if ((tid & 31) == 0) red[tid >> 5] = lsum;
    __syncthreads();
    if (tid < 32) {
        float v = (tid < 8) ? red[tid] : 0.f;
#pragma unroll
        for (int o = 4; o; o >>= 1)
            v += __shfl_xor_sync(0xffffffffu, v, o);
        if (tid == 0) red[0] = v;
    }
    __syncthreads();
    const float inv = 1.f / red[0];

    for (int i = tid * 4; i < SEQ; i += 256 * 4) {
        float4 v = *(float4*)&buf[i];
        v.x *= inv; v.y *= inv; v.z *= inv; v.w *= inv;
        uint32_t h[2], l[2];
        h[0] = pack_hi(v.x, v.y, l[0]);
        h[1] = pack_hi(v.z, v.w, l[1]);
        *(uint2*)(prow + i)       = *(uint2*)h;
        *(uint2*)(prow + SEQ + i) = *(uint2*)l;
    }
}

// ===========================================================================
// Launch
// ===========================================================================
extern "C" void kernel_launch(void* const* d_in, const int* in_sizes, int n_in,
                              void* d_out, int out_size)
{
    const float* X    = (const float*)d_in[0];
    const float* mask = (const float*)d_in[1];
    const float* Wq   = (const float*)d_in[2];
    const float* bq   = (const float*)d_in[3];
    const float* Wk   = (const float*)d_in[4];
    const float* bk   = (const float*)d_in[5];
    const float* Wv   = (const float*)d_in[6];
    const float* bv   = (const float*)d_in[7];
    float* out = (float*)d_out;

    cudaFuncSetAttribute(gemm_hmma, cudaFuncAttributeMaxDynamicSharedMemorySize,
                         GEMM_SMEM);

    // 1) hi/lo converts of inputs (vectorized, 8 elem/thread)
    {
        const size_t nX = (size_t)MROWS * HID;
        const size_t nW = (size_t)HID * HID;
        cvt_hilo8<<<(unsigned)(nX / 8 / 256), 256>>>(X,  SEL_XHL, HID, nX);
        cvt_hilo8<<<(unsigned)(nW / 8 / 256), 256>>>(Wq, SEL_WQ,  HID, nW);
        cvt_hilo8<<<(unsigned)(nW / 8 / 256), 256>>>(Wk, SEL_WK,  HID, nW);
        cvt_hilo8<<<(unsigned)(nW / 8 / 256), 256>>>(Wv, SEL_WV,  HID, nW);
    }

    // 2) QKV projections. Q,K: fused bf16 hi/lo epilogue. V: fp32 (for transpose).
    {
        dim3 g(HID / 128, MROWS / 128, 1);
        gemm_hmma<<<g, 256, GEMM_SMEM>>>(SEL_XHL, SEL_WQ, bq, 1, SEL_QHL, nullptr,
                                         nullptr, 0.f, HID, HID, 0, 0, 0);
        gemm_hmma<<<g, 256, GEMM_SMEM>>>(SEL_XHL, SEL_WK, bk, 1, SEL_KHL, nullptr,
                                         nullptr, 0.f, HID, HID, 0, 0, 0);
        gemm_hmma<<<g, 256, GEMM_SMEM>>>(SEL_XHL, SEL_WV, bv, 0, FSEL_VF, nullptr,
                                         nullptr, 0.f, HID, HID, 0, 0, 0);
    }

    // 3) Transpose + split V
    transpose_cvt_v<<<dim3(SEQ / 32, HID / 32, BATCH), 256>>>();

    // 4) Scores = (Q @ K^T) * scale + mask  (fused epilogue) -> g_Sf
    {
        dim3 g(SEQ / 128, SEQ / 128, BATCH);
        gemm_hmma<<<g, 256, GEMM_SMEM>>>(SEL_QHL, SEL_KHL, nullptr, 2, FSEL_SF, nullptr,
                                         mask, 0.08838834764831845f,
                                         HID, SEQ,
                                         (size_t)SEQ * KX, (size_t)SEQ * KX,
                                         (size_t)SEQ * SEQ);
    }

    // 5) Softmax -> g_Phl (bf16 hi/lo)
    softmax_rows<<<MROWS, 256>>>();

    // 6) Context = P @ Vt^T per batch -> d_out
    {
        dim3 g(HID / 128, SEQ / 128, BATCH);
        gemm_hmma<<<g, 256, GEMM_SMEM>>>(SEL_PHL, SEL_VTHL, nullptr, 0, -1, out,
                                         nullptr, 0.f, SEQ, HID,
                                         (size_t)SEQ * KPV, (size_t)HID * KPV,
                                         (size_t)SEQ * HID);
    }
}

// round 11
// speedup vs baseline: 2.9590x; 1.1169x over previous
#include <cuda_runtime.h>
#include <cuda_bf16.h>
#include <cstdint>

// ===========================================================================
// MainModelAttention via legacy tensor cores (mma.sync bf16, plain sm_80 PTX).
// context = softmax((X Wq^T + bq)(X Wk^T + bk)^T / sqrt(128) + mask)(X Wv^T+bv)
// B=2, S=4096, H=2048, fp32 I/O.
//
// Precision: fp32 x = hi + lo (bf16 each), rows stored [hi(0..K-1)|lo(K..2K-1)].
// GEMM accumulates hi*hi + hi*lo + lo*hi in fp32 -> ~2^-18 product error.
//
// R11: 3-stage cp.async ring (one barrier per K-chunk; write target is two
// barriers from its last reader) + kh-software-pipelined ldmatrix fragments.
// ===========================================================================

#define BATCH 2
#define SEQ   4096
#define HID   2048
#define MROWS (BATCH*SEQ)   // 8192
#define KX    (2*HID)
#define KPV   (2*SEQ)

// ---- scratch (__device__ globals; allocation-free) ----
__device__ __align__(256) __nv_bfloat16 g_Xhl[(size_t)MROWS * KX];
__device__ __align__(256) __nv_bfloat16 g_Whl[3][(size_t)HID * KX];
__device__ __align__(256) float         g_Vf[(size_t)MROWS * HID];
__device__ __align__(256) __nv_bfloat16 g_Qhl[(size_t)MROWS * KX];
__device__ __align__(256) __nv_bfloat16 g_Khl[(size_t)MROWS * KX];
__device__ __align__(256) __nv_bfloat16 g_Vthl[(size_t)BATCH * HID * KPV];
__device__ __align__(256) float         g_Sf[(size_t)BATCH * SEQ * SEQ];
__device__ __align__(256) __nv_bfloat16 g_Phl[(size_t)BATCH * SEQ * KPV];

enum { SEL_XHL = 0, SEL_WQ, SEL_WK, SEL_WV, SEL_QHL, SEL_KHL, SEL_VTHL, SEL_PHL };
enum { FSEL_VF = 0, FSEL_SF };

__device__ __forceinline__ __nv_bfloat16* bselw(int s) {
    switch (s) {
        case SEL_XHL:  return g_Xhl;
        case SEL_WQ:   return g_Whl[0];
        case SEL_WK:   return g_Whl[1];
        case SEL_WV:   return g_Whl[2];
        case SEL_QHL:  return g_Qhl;
        case SEL_KHL:  return g_Khl;
        case SEL_VTHL: return g_Vthl;
        default:       return g_Phl;
    }
}
__device__ __forceinline__ float* fselw(int s, float* ext) {
    switch (s) {
        case FSEL_VF: return g_Vf;
        case FSEL_SF: return g_Sf;
        default:      return ext;
    }
}

// ---- PTX helpers ----
__device__ __forceinline__ uint32_t smem_to_u32(const void* p) {
    uint32_t a;
    asm("{ .reg .u64 t; cvta.to.shared.u64 t, %1; cvt.u32.u64 %0, t; }"
        : "=r"(a) : "l"(p));
    return a;
}
#define CP_ASYNC16(dst, src) \
    asm volatile("cp.async.cg.shared.global [%0], [%1], 16;" :: "r"(dst), "l"(src))
#define CP_COMMIT() asm volatile("cp.async.commit_group;" ::: "memory")
#define CP_WAIT0()  asm volatile("cp.async.wait_group 0;" ::: "memory")
#define CP_WAIT1()  asm volatile("cp.async.wait_group 1;" ::: "memory")

__device__ __forceinline__ void ldsm4(uint32_t r[4], uint32_t a) {
    asm volatile("ldmatrix.sync.aligned.m8n8.x4.shared.b16 {%0,%1,%2,%3}, [%4];"
                 : "=r"(r[0]), "=r"(r[1]), "=r"(r[2]), "=r"(r[3]) : "r"(a));
}
__device__ __forceinline__ void mma_bf16(float d[4], const uint32_t a[4],
                                         const uint32_t b0, const uint32_t b1) {
    asm volatile(
        "mma.sync.aligned.m16n8k16.row.col.f32.bf16.bf16.f32 "
        "{%0,%1,%2,%3}, {%4,%5,%6,%7}, {%8,%9}, {%0,%1,%2,%3};"
        : "+f"(d[0]), "+f"(d[1]), "+f"(d[2]), "+f"(d[3])
        : "r"(a[0]), "r"(a[1]), "r"(a[2]), "r"(a[3]), "r"(b0), "r"(b1));
}

__device__ __forceinline__ uint32_t pack_hi(float a, float b, uint32_t& lo) {
    __nv_bfloat16 ha = __float2bfloat16(a);
    __nv_bfloat16 hb = __float2bfloat16(b);
    __nv_bfloat162 l;
    l.x = __float2bfloat16(a - __bfloat162float(ha));
    l.y = __float2bfloat16(b - __bfloat162float(hb));
    lo = *reinterpret_cast<uint32_t*>(&l);
    __nv_bfloat162 h; h.x = ha; h.y = hb;
    return *reinterpret_cast<uint32_t*>(&h);
}

// ===========================================================================
// GEMM-NT bf16 hi/lo (HMMA): C[m,n] = sum_k (Ahi+Alo)[m,k]*(Bhi+Blo)[n,k]
// Tile 128x128, BK=64, 8 warps (2x4) of 64x32 warp tiles.
// 3-stage cp.async ring, ONE __syncthreads per chunk (write target of iter t
// was last read at iter t-2 -> two barriers of separation).
// ROWB=144: 144/16=9, 9 mod 8 = 1 -> 8 rows hit 8 distinct 16B banks ->
// conflict-free ldmatrix.
// Epilogue modes: 0 = fp32 (+bias); 1 = bf16 hi/lo into bselw(Csel);
//                 2 = fp32 * scale + mask[z*N + col].
// ===========================================================================
#define ROWB    144
#define TILE_B  (128 * ROWB)           // 18432
#define STAGE_B (4 * TILE_B)           // 73728 (Ahi,Alo,Bhi,Blo)
#define NSTAGE  3
#define GEMM_SMEM (NSTAGE * STAGE_B)   // 221184

__device__ __forceinline__ void stage_loads(
    uint32_t smStage, const __nv_bfloat16* Ahi, const __nv_bfloat16* Alo,
    const __nv_bfloat16* Bhi, const __nv_bfloat16* Blo, size_t ld, int tid)
{
#pragma unroll
    for (int j = 0; j < 4; j++) {
        const int within = j * 256 + tid;      // 0..1023
        const int r = within >> 3, c = within & 7;
        const size_t go = (size_t)r * ld + c * 8;
        const uint32_t so = (uint32_t)(r * ROWB + c * 16);
        CP_ASYNC16(smStage + 0 * TILE_B + so, Ahi + go);
        CP_ASYNC16(smStage + 1 * TILE_B + so, Alo + go);
        CP_ASYNC16(smStage + 2 * TILE_B + so, Bhi + go);
        CP_ASYNC16(smStage + 3 * TILE_B + so, Blo + go);
    }
}

__global__ void __launch_bounds__(256)
gemm_hmma(int Asel, int Bsel, const float* __restrict__ bias,
          int emode, int Csel, float* __restrict__ Cext,
          const float* __restrict__ mask, float scale,
          int Korig, int N, size_t sA, size_t sB, size_t sC)
{
    extern __shared__ __align__(16) char sm[];
    const uint32_t smb = smem_to_u32(sm);
    const int tid = threadIdx.x;
    const int lane = tid & 31, warp = tid >> 5;
    const size_t ld = (size_t)2 * Korig;

    const __nv_bfloat16* A = bselw(Asel) + blockIdx.z * sA + (size_t)blockIdx.y * 128 * ld;
    const __nv_bfloat16* B = bselw(Bsel) + blockIdx.z * sB + (size_t)blockIdx.x * 128 * ld;

    const int m0 = (warp >> 2) * 64;     // warp tile origin
    const int n0 = (warp & 3) * 32;

    const uint32_t aLane = (uint32_t)((m0 + (lane & 15)) * ROWB + ((lane >> 4) << 4));
    const uint32_t bLane = (uint32_t)((n0 + ((lane >> 4) << 3) + (lane & 7)) * ROWB
                                      + (((lane >> 3) & 1) << 4));

    float acc[4][4][4];
#pragma unroll
    for (int i = 0; i < 4; i++)
#pragma unroll
        for (int j = 0; j < 4; j++)
#pragma unroll
            for (int q = 0; q < 4; q++) acc[i][j][q] = 0.f;

    // Double-buffered register fragments (kh software pipeline).
    uint32_t ah[2][4][4], al[2][4][4], bh[2][2][4], bl[2][2][4];

    const int T = Korig / 64;
    // Prologue: stage chunk 0 into ring slot 0.
    stage_loads(smb, A, A + Korig, B, B + Korig, ld, tid);
    CP_COMMIT();

    int stageIdx = 0;       // ring slot of chunk t
    for (int t = 0; t < T; t++) {
        if (t + 1 < T) {
            const int kt = (t + 1) * 64;
            const int nslot = (stageIdx + 1 == NSTAGE) ? 0 : stageIdx + 1;
            stage_loads(smb + nslot * STAGE_B,
                        A + kt, A + Korig + kt, B + kt, B + Korig + kt, ld, tid);
            CP_COMMIT();
            CP_WAIT1();      // chunk t complete; chunk t+1 in flight
        } else {
            CP_WAIT0();
        }
        __syncthreads();     // single barrier per chunk (3-stage ring makes
                             // buffer reuse two barriers away from last read)

        const uint32_t stage = smb + stageIdx * STAGE_B;
        const uint32_t aBase = stage + aLane;
        const uint32_t bBase = stage + 2 * TILE_B + bLane;

        // Load kh=0 fragments into slot 0.
#pragma unroll
        for (int mt = 0; mt < 4; mt++) {
            ldsm4(ah[0][mt], aBase + mt * (16 * ROWB));
            ldsm4(al[0][mt], aBase + mt * (16 * ROWB) + TILE_B);
        }
#pragma unroll
        for (int nt = 0; nt < 2; nt++) {
            ldsm4(bh[0][nt], bBase + nt * (16 * ROWB));
            ldsm4(bl[0][nt], bBase + nt * (16 * ROWB) + TILE_B);
        }

#pragma unroll
        for (int kh = 0; kh < 4; kh++) {
            const int cur = kh & 1, nxt = cur ^ 1;
            if (kh < 3) {
                const uint32_t aN = aBase + (kh + 1) * 32;
                const uint32_t bN = bBase + (kh + 1) * 32;
#pragma unroll
                for (int mt = 0; mt < 4; mt++) {
                    ldsm4(ah[nxt][mt], aN + mt * (16 * ROWB));
                    ldsm4(al[nxt][mt], aN + mt * (16 * ROWB) + TILE_B);
                }
#pragma unroll
                for (int nt = 0; nt < 2; nt++) {
                    ldsm4(bh[nxt][nt], bN + nt * (16 * ROWB));
                    ldsm4(bl[nxt][nt], bN + nt * (16 * ROWB) + TILE_B);
                }
            }
            // pass 1: hi*hi
#pragma unroll
            for (int mt = 0; mt < 4; mt++)
#pragma unroll
                for (int n8 = 0; n8 < 4; n8++)
                    mma_bf16(acc[mt][n8], ah[cur][mt],
                             bh[cur][n8 >> 1][(n8 & 1) * 2],
                             bh[cur][n8 >> 1][(n8 & 1) * 2 + 1]);
            // pass 2: hi*lo
#pragma unroll
            for (int mt = 0; mt < 4; mt++)
#pragma unroll
                for (int n8 = 0; n8 < 4; n8++)
                    mma_bf16(acc[mt][n8], ah[cur][mt],
                             bl[cur][n8 >> 1][(n8 & 1) * 2],
                             bl[cur][n8 >> 1][(n8 & 1) * 2 + 1]);
            // pass 3: lo*hi
#pragma unroll
            for (int mt = 0; mt < 4; mt++)
#pragma unroll
                for (int n8 = 0; n8 < 4; n8++)
                    mma_bf16(acc[mt][n8], al[cur][mt],
                             bh[cur][n8 >> 1][(n8 & 1) * 2],
                             bh[cur][n8 >> 1][(n8 & 1) * 2 + 1]);
        }
        stageIdx = (stageIdx + 1 == NSTAGE) ? 0 : stageIdx + 1;
    }

    // Epilogue. Fragment: c0,c1 = (row g, col 2t / 2t+1); c2,c3 = row g+8.
    const int g = lane >> 2, tq = lane & 3;
    if (emode == 1) {
        // bf16 hi/lo output rows of width 2N: [hi | lo]
        __nv_bfloat16* O = bselw(Csel) + blockIdx.z * sC;
        const size_t W2 = (size_t)2 * N;
#pragma unroll
        for (int mt = 0; mt < 4; mt++) {
            const size_t r0 = (size_t)blockIdx.y * 128 + m0 + mt * 16 + g;
#pragma unroll
            for (int n8 = 0; n8 < 4; n8++) {
                const size_t col = (size_t)blockIdx.x * 128 + n0 + n8 * 8 + 2 * tq;
                float b0 = 0.f, b1 = 0.f;
                if (bias) { b0 = bias[col]; b1 = bias[col + 1]; }
                uint32_t lo0, lo1;
                const uint32_t h0 = pack_hi(acc[mt][n8][0] + b0, acc[mt][n8][1] + b1, lo0);
                const uint32_t h1 = pack_hi(acc[mt][n8][2] + b0, acc[mt][n8][3] + b1, lo1);
                *(uint32_t*)(O + r0 * W2 + col)             = h0;
                *(uint32_t*)(O + r0 * W2 + N + col)         = lo0;
                *(uint32_t*)(O + (r0 + 8) * W2 + col)       = h1;
                *(uint32_t*)(O + (r0 + 8) * W2 + N + col)   = lo1;
            }
        }
    } else {
        float* C = fselw(Csel, Cext) + blockIdx.z * sC;
#pragma unroll
        for (int mt = 0; mt < 4; mt++) {
            const size_t r0 = (size_t)blockIdx.y * 128 + m0 + mt * 16 + g;
#pragma unroll
            for (int n8 = 0; n8 < 4; n8++) {
                const size_t col = (size_t)blockIdx.x * 128 + n0 + n8 * 8 + 2 * tq;
                float b0 = 0.f, b1 = 0.f;
                if (emode == 2) {
                    b0 = mask[(size_t)blockIdx.z * N + col];
                    b1 = mask[(size_t)blockIdx.z * N + col + 1];
                } else if (bias) {
                    b0 = bias[col]; b1 = bias[col + 1];
                }
                const float s = (emode == 2) ? scale : 1.f;
                float2 v0 = { acc[mt][n8][0] * s + b0, acc[mt][n8][1] * s + b1 };
                float2 v1 = { acc[mt][n8][2] * s + b0, acc[mt][n8][3] * s + b1 };
                *(float2*)(C + r0 * N + col) = v0;
                *(float2*)(C + (r0 + 8) * N + col) = v1;
            }
        }
    }
}

// ===========================================================================
// fp32 -> bf16 hi/lo convert, 8 elements/thread (vectorized).
// ===========================================================================
__global__ void __launch_bounds__(256)
cvt_hilo8(const float* __restrict__ in, int outSel, int C, size_t n)
{
    const size_t i = ((size_t)blockIdx.x * 256 + threadIdx.x) * 8;
    if (i >= n) return;
    __nv_bfloat16* out = bselw(outSel);
    const size_t r = i / (size_t)C, c = i - r * (size_t)C;

    float4 v0 = *(const float4*)(in + i);
    float4 v1 = *(const float4*)(in + i + 4);
    uint32_t h[4], l[4];
    h[0] = pack_hi(v0.x, v0.y, l[0]);
    h[1] = pack_hi(v0.z, v0.w, l[1]);
    h[2] = pack_hi(v1.x, v1.y, l[2]);
    h[3] = pack_hi(v1.z, v1.w, l[3]);
    __nv_bfloat16* oh = out + r * (size_t)(2 * C) + c;
    *(uint4*)oh       = *(uint4*)h;
    *(uint4*)(oh + C) = *(uint4*)l;
}

// ===========================================================================
// V transpose + hi/lo: Vf [b][s][h] -> Vthl [b][h][hi(s)|lo(s)]
// ===========================================================================
__global__ void __launch_bounds__(256)
transpose_cvt_v()
{
    __shared__ float tile[32][33];
    const int zb = blockIdx.z;
    const float* in = g_Vf + (size_t)zb * SEQ * HID;
    __nv_bfloat16* out = g_Vthl + (size_t)zb * HID * KPV;
    const int s0 = blockIdx.x * 32, h0 = blockIdx.y * 32;
    const int tx = threadIdx.x & 31, ty = threadIdx.x >> 5;
#pragma unroll
    for (int j = 0; j < 32; j += 8)
        tile[ty + j][tx] = in[(size_t)(s0 + ty + j) * HID + h0 + tx];
    __syncthreads();
#pragma unroll
    for (int j = 0; j < 32; j += 8) {
        float x = tile[tx][ty + j];
        __nv_bfloat16 h = __float2bfloat16(x);
        __nv_bfloat16 lo = __float2bfloat16(x - __bfloat162float(h));
        out[(size_t)(h0 + ty + j) * KPV + (s0 + tx)] = h;
        out[(size_t)(h0 + ty + j) * KPV + SEQ + (s0 + tx)] = lo;
    }
}

// ===========================================================================
// Row softmax over pre-scaled+masked scores: P = softmax(S) as bf16 hi/lo.
// ===========================================================================
__global__ void __launch_bounds__(256)
softmax_rows()
{
    __shared__ float buf[SEQ];
    __shared__ float red[8];

    const int row = blockIdx.x;
    const float* srow = g_Sf + (size_t)row * SEQ;
    __nv_bfloat16* prow = g_Phl + (size_t)row * KPV;
    const int tid = threadIdx.x;

    float lmax = -3.4028235e38f;
    for (int i = tid * 4; i < SEQ; i += 256 * 4) {
        float4 v = *(const float4*)(srow + i);
        *(float4*)&buf[i] = v;
        lmax = fmaxf(lmax, fmaxf(fmaxf(v.x, v.y), fmaxf(v.z, v.w)));
    }
#pragma unroll
    for (int o = 16; o; o >>= 1)
        lmax = fmaxf(lmax, __shfl_xor_sync(0xffffffffu, lmax, o));
    if ((tid & 31) == 0) red[tid >> 5] = lmax;
    __syncthreads();
    if (tid < 32) {
        float v = (tid < 8) ? red[tid] : -3.4028235e38f;
#pragma unroll
        for (int o = 4; o; o >>= 1)
            v = fmaxf(v, __shfl_xor_sync(0xffffffffu, v, o));
        if (tid == 0) red[0] = v;
    }
    __syncthreads();
    const float bmax = red[0];
    __syncthreads();

    float lsum = 0.f;
    for (int i = tid * 4; i < SEQ; i += 256 * 4) {
        float4 v = *(float4*)&buf[i];
        v.x = __expf(v.x - bmax); v.y = __expf(v.y - bmax);
        v.z = __expf(v.z - bmax); v.w = __expf(v.w - bmax);
        *(float4*)&buf[i] = v;
        lsum += v.x + v.y + v.z + v.w;
    }
#pragma unroll
    for (int o = 16; o; o >>= 1)
        lsum += __shfl_xor_sync(0xffffffffu, lsum, o);
    if ((tid & 31) == 0) red[tid >> 5] = lsum;
    __syncthreads();
    if (tid < 32) {
        float v = (tid < 8) ? red[tid] : 0.f;
#pragma unroll
        for (int o = 4; o; o >>= 1)
            v += __shfl_xor_sync(0xffffffffu, v, o);
        if (tid == 0) red[0] = v;
    }
    __syncthreads();
    const float inv = 1.f / red[0];

    for (int i = tid * 4; i < SEQ; i += 256 * 4) {
        float4 v = *(float4*)&buf[i];
        v.x *= inv; v.y *= inv; v.z *= inv; v.w *= inv;
        uint32_t h[2], l[2];
        h[0] = pack_hi(v.x, v.y, l[0]);
        h[1] = pack_hi(v.z, v.w, l[1]);
        *(uint2*)(prow + i)       = *(uint2*)h;
        *(uint2*)(prow + SEQ + i) = *(uint2*)l;
    }
}

// ===========================================================================
// Launch
// ===========================================================================
extern "C" void kernel_launch(void* const* d_in, const int* in_sizes, int n_in,
                              void* d_out, int out_size)
{
    const float* X    = (const float*)d_in[0];
    const float* mask = (const float*)d_in[1];
    const float* Wq   = (const float*)d_in[2];
    const float* bq   = (const float*)d_in[3];
    const float* Wk   = (const float*)d_in[4];
    const float* bk   = (const float*)d_in[5];
    const float* Wv   = (const float*)d_in[6];
    const float* bv   = (const float*)d_in[7];
    float* out = (float*)d_out;

    cudaFuncSetAttribute(gemm_hmma, cudaFuncAttributeMaxDynamicSharedMemorySize,
                         GEMM_SMEM);

    // 1) hi/lo converts of inputs (vectorized, 8 elem/thread)
    {
        const size_t nX = (size_t)MROWS * HID;
        const size_t nW = (size_t)HID * HID;
        cvt_hilo8<<<(unsigned)(nX / 8 / 256), 256>>>(X,  SEL_XHL, HID, nX);
        cvt_hilo8<<<(unsigned)(nW / 8 / 256), 256>>>(Wq, SEL_WQ,  HID, nW);
        cvt_hilo8<<<(unsigned)(nW / 8 / 256), 256>>>(Wk, SEL_WK,  HID, nW);
        cvt_hilo8<<<(unsigned)(nW / 8 / 256), 256>>>(Wv, SEL_WV,  HID, nW);
    }

    // 2) QKV projections. Q,K: fused bf16 hi/lo epilogue. V: fp32 (for transpose).
    {
        dim3 g(HID / 128, MROWS / 128, 1);
        gemm_hmma<<<g, 256, GEMM_SMEM>>>(SEL_XHL, SEL_WQ, bq, 1, SEL_QHL, nullptr,
                                         nullptr, 0.f, HID, HID, 0, 0, 0);
        gemm_hmma<<<g, 256, GEMM_SMEM>>>(SEL_XHL, SEL_WK, bk, 1, SEL_KHL, nullptr,
                                         nullptr, 0.f, HID, HID, 0, 0, 0);
        gemm_hmma<<<g, 256, GEMM_SMEM>>>(SEL_XHL, SEL_WV, bv, 0, FSEL_VF, nullptr,
                                         nullptr, 0.f, HID, HID, 0, 0, 0);
    }

    // 3) Transpose + split V
    transpose_cvt_v<<<dim3(SEQ / 32, HID / 32, BATCH), 256>>>();

    // 4) Scores = (Q @ K^T) * scale + mask  (fused epilogue) -> g_Sf
    {
        dim3 g(SEQ / 128, SEQ / 128, BATCH);
        gemm_hmma<<<g, 256, GEMM_SMEM>>>(SEL_QHL, SEL_KHL, nullptr, 2, FSEL_SF, nullptr,
                                         mask, 0.08838834764831845f,
                                         HID, SEQ,
                                         (size_t)SEQ * KX, (size_t)SEQ * KX,
                                         (size_t)SEQ * SEQ);
    }

    // 5) Softmax -> g_Phl (bf16 hi/lo)
    softmax_rows<<<MROWS, 256>>>();

    // 6) Context = P @ Vt^T per batch -> d_out
    {
        dim3 g(HID / 128, SEQ / 128, BATCH);
        gemm_hmma<<<g, 256, GEMM_SMEM>>>(SEL_PHL, SEL_VTHL, nullptr, 0, -1, out,
                                         nullptr, 0.f, SEQ, HID,
                                         (size_t)SEQ * KPV, (size_t)HID * KPV,
                                         (size_t)SEQ * HID);
    }
}